// round 4
// baseline (speedup 1.0000x reference)
#include <cuda_runtime.h>
#include <cstdint>
#include <math.h>

typedef unsigned long long u64;

#define SA_N  8192
#define SA_D  1024
#define SA_DH 128

#define BM 64
#define BN 64
#define QPAD 132          // Q tile row stride (floats)
#define KPADK 130         // K tile row stride: 130 ≡ 2 mod 32 banks -> conflict-free stride-1-row access
#define VPAD 132          // V tile row stride
#define PPAD 68           // P tile row stride

// smem layout (floats)
#define QS_OFF 0
#define KS_OFF 8448                  // 64*132
#define KTILE  8320                  // 64*130
#define VS_OFF (KS_OFF + 2*KTILE)    // 25088
#define VTILE  8448                  // 64*132
#define PS_OFF (VS_OFF + 2*VTILE)    // 41984
#define SMEM_FLOATS (PS_OFF + 64*PPAD)   // 46336
#define SMEM_BYTES (SMEM_FLOATS*4)       // 185344

__device__ float g_Q[SA_N*SA_DH];
__device__ float g_K[SA_N*SA_DH];
__device__ float g_V[SA_N*SA_DH];

// ---- f32x2 packed math (Blackwell) --------------------------------------
__device__ __forceinline__ void ffma2(u64& d, u64 a, u64 b) {
    asm("fma.rn.f32x2 %0, %1, %2, %0;" : "+l"(d) : "l"(a), "l"(b));
}
__device__ __forceinline__ u64 pack2(float x) {
    u64 d; asm("mov.b64 %0, {%1, %1};" : "=l"(d) : "f"(x)); return d;
}
__device__ __forceinline__ float2 unpack2(u64 d) {
    float2 f; asm("mov.b64 {%0, %1}, %2;" : "=f"(f.x), "=f"(f.y) : "l"(d)); return f;
}
__device__ __forceinline__ void fmul2(u64& d, u64 a) {
    asm("mul.rn.f32x2 %0, %0, %1;" : "+l"(d) : "l"(a));
}

// ---- cp.async -----------------------------------------------------------
__device__ __forceinline__ void cp_async16(uint32_t dst, const void* src) {
    asm volatile("cp.async.cg.shared.global [%0], [%1], 16;\n" :: "r"(dst), "l"(src));
}
__device__ __forceinline__ void cp_async8(uint32_t dst, const void* src) {
    asm volatile("cp.async.ca.shared.global [%0], [%1], 8;\n" :: "r"(dst), "l"(src));
}
__device__ __forceinline__ void cp_commit() { asm volatile("cp.async.commit_group;\n" ::); }
__device__ __forceinline__ void cp_wait0()  { asm volatile("cp.async.wait_group 0;\n" ::); }

// ---------------------------------------------------------------------------
// Kernel 1: QKV projection with FFMA2 (col-paired). grid=(N/64,3), block=256.
// ---------------------------------------------------------------------------
#define P1_BK 32
__global__ __launch_bounds__(256, 1)
void qkv_kernel(const float* __restrict__ x,
                const float* __restrict__ Wq,
                const float* __restrict__ Wk,
                const float* __restrict__ Wv) {
    __shared__ float Xs[64][P1_BK + 4];
    __shared__ float Ws[P1_BK][SA_DH + 4];

    const float* W; float* Y; float scale;
    if (blockIdx.y == 0)      { W = Wq; Y = g_Q; scale = 0.08838834764831845f; }
    else if (blockIdx.y == 1) { W = Wk; Y = g_K; scale = 1.0f; }
    else                      { W = Wv; Y = g_V; scale = 1.0f; }

    const int tid = threadIdx.x;
    const int ty = tid >> 4;      // 4 rows each
    const int tx = tid & 15;      // cols 2tx+32p (+1)
    const int row0 = blockIdx.x * 64;

    u64 acc2[4][4];
#pragma unroll
    for (int r = 0; r < 4; r++)
#pragma unroll
        for (int p = 0; p < 4; p++) acc2[r][p] = 0ull;

    for (int k0 = 0; k0 < SA_D; k0 += P1_BK) {
        __syncthreads();
#pragma unroll
        for (int i = tid; i < 64 * 8; i += 256) {
            int r = i >> 3, c4 = i & 7;
            float4 v = *(const float4*)&x[(size_t)(row0 + r) * SA_D + k0 + c4 * 4];
            *(float4*)&Xs[r][c4 * 4] = v;
        }
#pragma unroll
        for (int i = tid; i < 32 * 32; i += 256) {
            int r = i >> 5, c4 = i & 31;
            float4 v = *(const float4*)&W[(size_t)(k0 + r) * SA_DH + c4 * 4];
            *(float4*)&Ws[r][c4 * 4] = v;
        }
        __syncthreads();

#pragma unroll 8
        for (int kk = 0; kk < P1_BK; kk++) {
            u64 xd[4], w2[4];
#pragma unroll
            for (int rr = 0; rr < 4; rr++) xd[rr] = pack2(Xs[ty * 4 + rr][kk]);
#pragma unroll
            for (int p = 0; p < 4; p++)
                w2[p] = *(const u64*)&Ws[kk][tx * 2 + p * 32];
#pragma unroll
            for (int rr = 0; rr < 4; rr++)
#pragma unroll
                for (int p = 0; p < 4; p++)
                    ffma2(acc2[rr][p], xd[rr], w2[p]);
        }
    }

#pragma unroll
    for (int rr = 0; rr < 4; rr++) {
        size_t row = row0 + ty * 4 + rr;
#pragma unroll
        for (int p = 0; p < 4; p++) {
            float2 f = unpack2(acc2[rr][p]);
            f.x *= scale; f.y *= scale;
            *(float2*)&Y[row * SA_DH + tx * 2 + p * 32] = f;
        }
    }
}

// ---------------------------------------------------------------------------
// Kernel 2: fused flash attention, FFMA2 everywhere. grid=128, block=256.
// ---------------------------------------------------------------------------
__device__ __forceinline__ void load_kv_chunk(float* smem, int buf, int t, int tid) {
    uint32_t kdst = (uint32_t)__cvta_generic_to_shared(&smem[KS_OFF + buf * KTILE]);
    uint32_t vdst = (uint32_t)__cvta_generic_to_shared(&smem[VS_OFF + buf * VTILE]);
    const float* ks = g_K + (size_t)t * BN * SA_DH;
    const float* vs = g_V + (size_t)t * BN * SA_DH;
    // K: 64x128 floats as 4096 8B words (row stride 130 floats = 520B, 8B-aligned)
#pragma unroll
    for (int i = 0; i < 16; i++) {
        int c = tid + i * 256;
        int r = c >> 6, w = c & 63;
        cp_async8(kdst + (uint32_t)(r * KPADK + w * 2) * 4, ks + r * SA_DH + w * 2);
    }
    // V: 64x128 floats as 2048 16B words
#pragma unroll
    for (int i = 0; i < 8; i++) {
        int c = tid + i * 256;
        int r = c >> 5, w = c & 31;
        cp_async16(vdst + (uint32_t)(r * VPAD + w * 4) * 4, vs + r * SA_DH + w * 4);
    }
}

__global__ __launch_bounds__(256, 1)
void attn_kernel(float* __restrict__ out) {
    extern __shared__ float smem[];
    const int tid = threadIdx.x;
    const int ty = tid >> 4;   // 4 query rows each
    const int tx = tid & 15;
    const int row0 = blockIdx.x * BM;

    // Q tile + first K/V chunk
    {
        uint32_t qdst = (uint32_t)__cvta_generic_to_shared(&smem[QS_OFF]);
        const float* qs = g_Q + (size_t)row0 * SA_DH;
#pragma unroll
        for (int i = 0; i < 8; i++) {
            int c = tid + i * 256;
            int r = c >> 5, w = c & 31;
            cp_async16(qdst + (uint32_t)(r * QPAD + w * 4) * 4, qs + r * SA_DH + w * 4);
        }
        load_kv_chunk(smem, 0, 0, tid);
        cp_commit();
    }

    u64 o2[4][4];              // rows rr, col-pairs (2tx+32u, +1)
    float m[4], l[4];
#pragma unroll
    for (int rr = 0; rr < 4; rr++) {
        m[rr] = -INFINITY; l[rr] = 0.0f;
#pragma unroll
        for (int u = 0; u < 4; u++) o2[rr][u] = 0ull;
    }

    const int NCHUNK = SA_N / BN;   // 128
    for (int t = 0; t < NCHUNK; t++) {
        const int buf = t & 1;
        cp_wait0();
        __syncthreads();
        if (t + 1 < NCHUNK) {
            load_kv_chunk(smem, buf ^ 1, t + 1, tid);
            cp_commit();
        }

        const float* Kb = &smem[KS_OFF + buf * KTILE];
        const float* Vb = &smem[VS_OFF + buf * VTILE];

        // ----- S = Q K^T : k-paired FFMA2, dual partial sums -----
        u64 s2[4][4];
#pragma unroll
        for (int rr = 0; rr < 4; rr++)
#pragma unroll
            for (int cc = 0; cc < 4; cc++) s2[rr][cc] = 0ull;

#pragma unroll 8
        for (int k4 = 0; k4 < 32; k4++) {      // 4 k-elems = 2 k-pairs per iter
            u64 q0[4], q1[4], kk0[4], kk1[4];
#pragma unroll
            for (int rr = 0; rr < 4; rr++) {
                ulonglong2 qv = *(const ulonglong2*)&smem[QS_OFF + (ty * 4 + rr) * QPAD + k4 * 4];
                q0[rr] = qv.x; q1[rr] = qv.y;
            }
#pragma unroll
            for (int cc = 0; cc < 4; cc++) {
                kk0[cc] = *(const u64*)&Kb[(tx + cc * 16) * KPADK + k4 * 4];
                kk1[cc] = *(const u64*)&Kb[(tx + cc * 16) * KPADK + k4 * 4 + 2];
            }
#pragma unroll
            for (int rr = 0; rr < 4; rr++)
#pragma unroll
                for (int cc = 0; cc < 4; cc++) {
                    ffma2(s2[rr][cc], q0[rr], kk0[cc]);
                    ffma2(s2[rr][cc], q1[rr], kk1[cc]);
                }
        }

        // ----- online softmax -----
#pragma unroll
        for (int rr = 0; rr < 4; rr++) {
            float sv[4];
#pragma unroll
            for (int cc = 0; cc < 4; cc++) {
                float2 f = unpack2(s2[rr][cc]);
                sv[cc] = f.x + f.y;
            }
            float mx = fmaxf(fmaxf(sv[0], sv[1]), fmaxf(sv[2], sv[3]));
#pragma unroll
            for (int d = 8; d >= 1; d >>= 1)
                mx = fmaxf(mx, __shfl_xor_sync(0xffffffffu, mx, d));
            float mn = fmaxf(m[rr], mx);
            float alpha = __expf(m[rr] - mn);
            m[rr] = mn;
            float rs = 0.0f;
#pragma unroll
            for (int cc = 0; cc < 4; cc++) {
                float p = __expf(sv[cc] - mn);
                sv[cc] = p;
                rs += p;
            }
#pragma unroll
            for (int d = 8; d >= 1; d >>= 1)
                rs += __shfl_xor_sync(0xffffffffu, rs, d);
            l[rr] = l[rr] * alpha + rs;
            u64 ad = pack2(alpha);
#pragma unroll
            for (int u = 0; u < 4; u++) fmul2(o2[rr][u], ad);
#pragma unroll
            for (int cc = 0; cc < 4; cc++)
                smem[PS_OFF + (ty * 4 + rr) * PPAD + tx + cc * 16] = sv[cc];
        }
        __syncthreads();

        // ----- O += P V : col-paired FFMA2 -----
#pragma unroll 4
        for (int j4 = 0; j4 < 16; j4++) {      // 4 keys per iter
            float pr[4][4];
#pragma unroll
            for (int rr = 0; rr < 4; rr++) {
                float4 pf = *(const float4*)&smem[PS_OFF + (ty * 4 + rr) * PPAD + j4 * 4];
                pr[rr][0] = pf.x; pr[rr][1] = pf.y; pr[rr][2] = pf.z; pr[rr][3] = pf.w;
            }
#pragma unroll
            for (int jj = 0; jj < 4; jj++) {
                u64 vv[4];
#pragma unroll
                for (int u = 0; u < 4; u++)
                    vv[u] = *(const u64*)&Vb[(j4 * 4 + jj) * VPAD + tx * 2 + u * 32];
#pragma unroll
                for (int rr = 0; rr < 4; rr++) {
                    u64 pd = pack2(pr[rr][jj]);
#pragma unroll
                    for (int u = 0; u < 4; u++)
                        ffma2(o2[rr][u], pd, vv[u]);
                }
            }
        }
    }

    // ----- epilogue -----
#pragma unroll
    for (int rr = 0; rr < 4; rr++) {
        float inv = 1.0f / l[rr];
        size_t row = row0 + ty * 4 + rr;
#pragma unroll
        for (int u = 0; u < 4; u++) {
            float2 f = unpack2(o2[rr][u]);
            f.x *= inv; f.y *= inv;
            *(float2*)&out[row * SA_DH + tx * 2 + u * 32] = f;
        }
    }
}

// ---------------------------------------------------------------------------
extern "C" void kernel_launch(void* const* d_in, const int* in_sizes, int n_in,
                              void* d_out, int out_size) {
    const float* x  = (const float*)d_in[0];
    const float* Wq = (const float*)d_in[1];
    const float* Wk = (const float*)d_in[2];
    const float* Wv = (const float*)d_in[3];
    float* out = (float*)d_out;

    cudaFuncSetAttribute(attn_kernel, cudaFuncAttributeMaxDynamicSharedMemorySize, SMEM_BYTES);

    qkv_kernel<<<dim3(SA_N / 64, 3), 256>>>(x, Wq, Wk, Wv);
    attn_kernel<<<SA_N / BM, 256, SMEM_BYTES>>>(out);
}

// round 6
// speedup vs baseline: 2.7246x; 2.7246x over previous
#include <cuda_runtime.h>
#include <cuda_fp16.h>
#include <cstdint>
#include <math.h>

typedef unsigned long long u64;

#define SA_N  8192
#define SA_D  1024
#define SA_DH 128
#define BM 64
#define BN 64
#define NC (SA_N/BN)

// fp16 operands produced by qkv kernel
__device__ __align__(16) __half g_qh[SA_N*SA_DH];
__device__ __align__(16) __half g_ql[SA_N*SA_DH];
__device__ __align__(16) __half g_kh[SA_N*SA_DH];
__device__ __align__(16) __half g_kl[SA_N*SA_DH];
__device__ __align__(16) __half g_v [SA_N*SA_DH];

// smem layout (bytes): Qhi 16K | Qlo 16K | 2 x {Khi 16K, Klo 16K, V 16K}
#define SQH 0
#define SQL 16384
#define SBUF 32768
#define BUFSZ 49152
#define SMEM_BYTES (SBUF + 2*BUFSZ)   // 131072

// swizzled byte offset inside a 64x128 fp16 tile (256B rows, 16B chunks)
#define SWZ(r, ch) ((uint32_t)((r)*256 + ((((ch) ^ ((r)&7)))<<4)))

__device__ __forceinline__ uint32_t smem_u32(const void* p) {
    uint32_t a;
    asm("{ .reg .u64 t; cvta.to.shared.u64 t, %1; cvt.u32.u64 %0, t; }" : "=r"(a) : "l"(p));
    return a;
}
__device__ __forceinline__ void cp_async16(uint32_t dst, const void* src) {
    asm volatile("cp.async.cg.shared.global [%0], [%1], 16;\n" :: "r"(dst), "l"(src));
}
__device__ __forceinline__ void cp_commit() { asm volatile("cp.async.commit_group;\n" ::); }
__device__ __forceinline__ void cp_wait0()  { asm volatile("cp.async.wait_group 0;\n" ::); }

__device__ __forceinline__ void ldmx4(uint32_t a, uint32_t r[4]) {
    asm volatile("ldmatrix.sync.aligned.m8n8.x4.shared.b16 {%0,%1,%2,%3}, [%4];"
        : "=r"(r[0]), "=r"(r[1]), "=r"(r[2]), "=r"(r[3]) : "r"(a));
}
__device__ __forceinline__ void ldmx4t(uint32_t a, uint32_t r[4]) {
    asm volatile("ldmatrix.sync.aligned.m8n8.x4.trans.shared.b16 {%0,%1,%2,%3}, [%4];"
        : "=r"(r[0]), "=r"(r[1]), "=r"(r[2]), "=r"(r[3]) : "r"(a));
}
__device__ __forceinline__ void mma16816(float c[4], const uint32_t a[4],
                                         uint32_t b0, uint32_t b1) {
    asm volatile("mma.sync.aligned.m16n8k16.row.col.f32.f16.f16.f32 "
        "{%0,%1,%2,%3}, {%4,%5,%6,%7}, {%8,%9}, {%0,%1,%2,%3};"
        : "+f"(c[0]), "+f"(c[1]), "+f"(c[2]), "+f"(c[3])
        : "r"(a[0]), "r"(a[1]), "r"(a[2]), "r"(a[3]), "r"(b0), "r"(b1));
}
__device__ __forceinline__ float ex2f(float x) {
    float r; asm("ex2.approx.ftz.f32 %0, %1;" : "=f"(r) : "f"(x)); return r;
}
__device__ __forceinline__ uint32_t f16x2(float hi, float lo) {
    uint32_t d; asm("cvt.rn.f16x2.f32 %0, %1, %2;" : "=r"(d) : "f"(hi), "f"(lo)); return d;
}
__device__ __forceinline__ float2 h2f2(uint32_t d) {
    __half2 h = *(__half2*)&d; return __half22float2(h);
}

// ---------------------------------------------------------------------------
// qkv: FFMA2 fp32 projection, epilogue emits fp16 hi/lo splits (+V fp16).
// Q pre-scaled by log2(e)/sqrt(128) so softmax runs in exp2 domain.
// ---------------------------------------------------------------------------
__device__ __forceinline__ void ffma2(u64& d, u64 a, u64 b) {
    asm("fma.rn.f32x2 %0, %1, %2, %0;" : "+l"(d) : "l"(a), "l"(b));
}
__device__ __forceinline__ u64 pack2f(float x) {
    u64 d; asm("mov.b64 %0, {%1, %1};" : "=l"(d) : "f"(x)); return d;
}
__device__ __forceinline__ float2 unpack2f(u64 d) {
    float2 f; asm("mov.b64 {%0, %1}, %2;" : "=f"(f.x), "=f"(f.y) : "l"(d)); return f;
}

#define P1_BK 32
__global__ __launch_bounds__(256, 1)
void qkv_kernel(const float* __restrict__ x, const float* __restrict__ Wq,
                const float* __restrict__ Wk, const float* __restrict__ Wv) {
    __shared__ float Xs[64][P1_BK + 4];
    __shared__ float Ws[P1_BK][SA_DH + 4];
    const float* W = (blockIdx.y == 0) ? Wq : (blockIdx.y == 1) ? Wk : Wv;
    const int tid = threadIdx.x, ty = tid >> 4, tx = tid & 15;
    const int row0 = blockIdx.x * 64;

    u64 acc2[4][4];
#pragma unroll
    for (int r = 0; r < 4; r++)
#pragma unroll
        for (int p = 0; p < 4; p++) acc2[r][p] = 0ull;

    for (int k0 = 0; k0 < SA_D; k0 += P1_BK) {
        __syncthreads();
#pragma unroll
        for (int i = tid; i < 64 * 8; i += 256) {
            int r = i >> 3, c4 = i & 7;
            *(float4*)&Xs[r][c4 * 4] = *(const float4*)&x[(size_t)(row0 + r) * SA_D + k0 + c4 * 4];
        }
#pragma unroll
        for (int i = tid; i < 32 * 32; i += 256) {
            int r = i >> 5, c4 = i & 31;
            *(float4*)&Ws[r][c4 * 4] = *(const float4*)&W[(size_t)(k0 + r) * SA_DH + c4 * 4];
        }
        __syncthreads();
#pragma unroll 8
        for (int kk = 0; kk < P1_BK; kk++) {
            u64 xd[4], w2[4];
#pragma unroll
            for (int rr = 0; rr < 4; rr++) xd[rr] = pack2f(Xs[ty * 4 + rr][kk]);
#pragma unroll
            for (int p = 0; p < 4; p++) w2[p] = *(const u64*)&Ws[kk][tx * 2 + p * 32];
#pragma unroll
            for (int rr = 0; rr < 4; rr++)
#pragma unroll
                for (int p = 0; p < 4; p++) ffma2(acc2[rr][p], xd[rr], w2[p]);
        }
    }

    const float qscale = (float)(1.4426950408889634 / 11.313708498984761);
#pragma unroll
    for (int rr = 0; rr < 4; rr++) {
        size_t row = row0 + ty * 4 + rr;
#pragma unroll
        for (int p = 0; p < 4; p++) {
            float2 f = unpack2f(acc2[rr][p]);
            int c0 = tx * 2 + p * 32;
            size_t idx = row * SA_DH + c0;
            if (blockIdx.y == 0) {
                float a = f.x * qscale, b = f.y * qscale;
                __half ah = __float2half_rn(a), bh = __float2half_rn(b);
                __half al = __float2half_rn(a - __half2float(ah));
                __half bl = __float2half_rn(b - __half2float(bh));
                *(__half2*)&g_qh[idx] = __halves2half2(ah, bh);
                *(__half2*)&g_ql[idx] = __halves2half2(al, bl);
            } else if (blockIdx.y == 1) {
                __half ah = __float2half_rn(f.x), bh = __float2half_rn(f.y);
                __half al = __float2half_rn(f.x - __half2float(ah));
                __half bl = __float2half_rn(f.y - __half2float(bh));
                *(__half2*)&g_kh[idx] = __halves2half2(ah, bh);
                *(__half2*)&g_kl[idx] = __halves2half2(al, bl);
            } else {
                *(__half2*)&g_v[idx] = __floats2half2_rn(f.x, f.y);
            }
        }
    }
}

// ---------------------------------------------------------------------------
// Fused flash attention via mma.sync fp16 (hi/lo split). grid=128, block=128.
// ---------------------------------------------------------------------------
__device__ __forceinline__ void load_chunk(uint32_t dst, int t, int tid) {
    const size_t key0 = (size_t)t * BN * SA_DH;
    const __half* kh = g_kh + key0;
    const __half* kl = g_kl + key0;
    const __half* v  = g_v  + key0;
#pragma unroll
    for (int i = 0; i < 8; i++) {
        int c = tid + i * 128;
        int r = c >> 4, ch = c & 15;
        uint32_t off = SWZ(r, ch);
        size_t src = (size_t)r * SA_DH + ch * 8;
        cp_async16(dst + off,         kh + src);
        cp_async16(dst + 16384 + off, kl + src);
        cp_async16(dst + 32768 + off, v  + src);
    }
}

__global__ __launch_bounds__(128, 1)
void attn_kernel(float* __restrict__ out) {
    extern __shared__ char smem[];
    const uint32_t sb = smem_u32(smem);
    const int tid = threadIdx.x, wid = tid >> 5, lane = tid & 31;
    const int g = lane >> 2, cq = lane & 3;
    const int row0 = blockIdx.x * BM;
    const int wm0 = wid * 16;

    // fragment address components
    const int rowq  = wm0 + (lane & 15);      // Q A-frag row
    const int chq0  = lane >> 4;              // Q k-half
    const int quarter = lane >> 3;
    const int kj_sub = quarter >> 1;          // K/V ntile sub-index
    const int k_half = quarter & 1;           // K k-half / V row-half
    const int rk = lane & 7;
    const int rvo = k_half * 8 + rk;          // V row offset within 16-key ktile

    // prologue: Q tiles + chunk 0
    {
        const __half* qh = g_qh + (size_t)row0 * SA_DH;
        const __half* ql = g_ql + (size_t)row0 * SA_DH;
#pragma unroll
        for (int i = 0; i < 8; i++) {
            int c = tid + i * 128;
            int r = c >> 4, ch = c & 15;
            uint32_t off = SWZ(r, ch);
            size_t src = (size_t)r * SA_DH + ch * 8;
            cp_async16(sb + SQH + off, qh + src);
            cp_async16(sb + SQL + off, ql + src);
        }
        load_chunk(sb + SBUF, 0, tid);
        cp_commit();
    }

    float o[16][4];
#pragma unroll
    for (int n = 0; n < 16; n++)
#pragma unroll
        for (int i = 0; i < 4; i++) o[n][i] = 0.0f;
    float m0 = -1e30f, m1 = -1e30f, l0 = 0.0f, l1 = 0.0f;

    for (int t = 0; t < NC; t++) {
        cp_wait0();
        __syncthreads();
        const uint32_t buf = sb + SBUF + (uint32_t)(t & 1) * BUFSZ;
        if (t + 1 < NC) {
            load_chunk(sb + SBUF + (uint32_t)((t + 1) & 1) * BUFSZ, t + 1, tid);
            cp_commit();
        }

        // ----- S = Q K^T (3 fp16 MMAs per tile: hh + hl + lh) -----
        float c[8][4];
#pragma unroll
        for (int j = 0; j < 8; j++)
#pragma unroll
            for (int i = 0; i < 4; i++) c[j][i] = 0.0f;

#pragma unroll
        for (int kt = 0; kt < 8; kt++) {
            uint32_t ah[4], al[4];
            ldmx4(sb + SQH + SWZ(rowq, kt * 2 + chq0), ah);
            ldmx4(sb + SQL + SWZ(rowq, kt * 2 + chq0), al);
            uint32_t bh[4][4], bl[4][4];
#pragma unroll
            for (int np = 0; np < 4; np++) {
                int j = np * 2 + kj_sub;
                uint32_t off = SWZ(j * 8 + rk, kt * 2 + k_half);
                ldmx4(buf + off, bh[np]);
                ldmx4(buf + 16384 + off, bl[np]);
            }
#pragma unroll
            for (int np = 0; np < 4; np++) {
                mma16816(c[2 * np],     ah, bh[np][0], bh[np][1]);
                mma16816(c[2 * np + 1], ah, bh[np][2], bh[np][3]);
            }
#pragma unroll
            for (int np = 0; np < 4; np++) {
                mma16816(c[2 * np],     ah, bl[np][0], bl[np][1]);
                mma16816(c[2 * np + 1], ah, bl[np][2], bl[np][3]);
            }
#pragma unroll
            for (int np = 0; np < 4; np++) {
                mma16816(c[2 * np],     al, bh[np][0], bh[np][1]);
                mma16816(c[2 * np + 1], al, bh[np][2], bh[np][3]);
            }
        }

        // ----- online softmax (log2 domain) -----
        float mx0 = -1e30f, mx1 = -1e30f;
#pragma unroll
        for (int j = 0; j < 8; j++) {
            mx0 = fmaxf(mx0, fmaxf(c[j][0], c[j][1]));
            mx1 = fmaxf(mx1, fmaxf(c[j][2], c[j][3]));
        }
        mx0 = fmaxf(mx0, __shfl_xor_sync(0xffffffffu, mx0, 1));
        mx0 = fmaxf(mx0, __shfl_xor_sync(0xffffffffu, mx0, 2));
        mx1 = fmaxf(mx1, __shfl_xor_sync(0xffffffffu, mx1, 1));
        mx1 = fmaxf(mx1, __shfl_xor_sync(0xffffffffu, mx1, 2));
        float nm0 = fmaxf(m0, mx0), nm1 = fmaxf(m1, mx1);
        float a0 = ex2f(m0 - nm0), a1 = ex2f(m1 - nm1);
        m0 = nm0; m1 = nm1;
        l0 *= a0; l1 *= a1;
#pragma unroll
        for (int n = 0; n < 16; n++) {
            o[n][0] *= a0; o[n][1] *= a0;
            o[n][2] *= a1; o[n][3] *= a1;
        }
        uint32_t pp[16];
#pragma unroll
        for (int j = 0; j < 8; j++) {
            float p0 = ex2f(c[j][0] - m0), p1 = ex2f(c[j][1] - m0);
            uint32_t pg = f16x2(p1, p0);             // lo=p0, hi=p1
            float2 fb = h2f2(pg); l0 += fb.x + fb.y; // l from rounded p
            pp[j * 2] = pg;
            float p2 = ex2f(c[j][2] - m1), p3 = ex2f(c[j][3] - m1);
            uint32_t ph = f16x2(p3, p2);
            float2 fc = h2f2(ph); l1 += fc.x + fc.y;
            pp[j * 2 + 1] = ph;
        }

        // ----- O += P V -----
#pragma unroll
        for (int kt = 0; kt < 4; kt++) {
            uint32_t aP[4] = { pp[(2 * kt) * 2], pp[(2 * kt) * 2 + 1],
                               pp[(2 * kt + 1) * 2], pp[(2 * kt + 1) * 2 + 1] };
#pragma unroll
            for (int np = 0; np < 8; np++) {
                uint32_t bv[4];
                ldmx4t(buf + 32768 + SWZ(kt * 16 + rvo, 2 * np + kj_sub), bv);
                mma16816(o[2 * np],     aP, bv[0], bv[1]);
                mma16816(o[2 * np + 1], aP, bv[2], bv[3]);
            }
        }
    }

    // ----- epilogue -----
    l0 += __shfl_xor_sync(0xffffffffu, l0, 1);
    l0 += __shfl_xor_sync(0xffffffffu, l0, 2);
    l1 += __shfl_xor_sync(0xffffffffu, l1, 1);
    l1 += __shfl_xor_sync(0xffffffffu, l1, 2);
    float i0 = 1.0f / l0, i1 = 1.0f / l1;
    const int ra = row0 + wm0 + g, rb = ra + 8;
#pragma unroll
    for (int n = 0; n < 16; n++) {
        int col = n * 8 + cq * 2;
        *(float2*)&out[(size_t)ra * SA_DH + col] = make_float2(o[n][0] * i0, o[n][1] * i0);
        *(float2*)&out[(size_t)rb * SA_DH + col] = make_float2(o[n][2] * i1, o[n][3] * i1);
    }
}

// ---------------------------------------------------------------------------
extern "C" void kernel_launch(void* const* d_in, const int* in_sizes, int n_in,
                              void* d_out, int out_size) {
    const float* x  = (const float*)d_in[0];
    const float* Wq = (const float*)d_in[1];
    const float* Wk = (const float*)d_in[2];
    const float* Wv = (const float*)d_in[3];
    float* out = (float*)d_out;

    cudaFuncSetAttribute(attn_kernel, cudaFuncAttributeMaxDynamicSharedMemorySize, SMEM_BYTES);

    qkv_kernel<<<dim3(SA_N / 64, 3), 256>>>(x, Wq, Wk, Wv);
    attn_kernel<<<SA_N / BM, 128, SMEM_BYTES>>>(out);
}

// round 7
// speedup vs baseline: 3.5468x; 1.3018x over previous
#include <cuda_runtime.h>
#include <cuda_fp16.h>
#include <cstdint>
#include <math.h>

typedef unsigned long long u64;

#define SA_N  8192
#define SA_D  1024
#define SA_DH 128
#define BM 64
#define BN 64
#define NC (SA_N/BN)

// fp16 operands
__device__ __align__(16) __half g_qh[SA_N*SA_DH];
__device__ __align__(16) __half g_ql[SA_N*SA_DH];
__device__ __align__(16) __half g_kh[SA_N*SA_DH];
__device__ __align__(16) __half g_kl[SA_N*SA_DH];
__device__ __align__(16) __half g_v [SA_N*SA_DH];
// fp16 split inputs for qkv gemm
__device__ __align__(16) __half g_xh[SA_N*SA_D];
__device__ __align__(16) __half g_xl[SA_N*SA_D];
__device__ __align__(16) __half g_wh[3*SA_D*SA_DH];
__device__ __align__(16) __half g_wl[3*SA_D*SA_DH];

// attn smem: Qhi 16K | Qlo 16K | 2 x {Khi 16K, Klo 16K, V 16K}
#define SQH 0
#define SQL 16384
#define SBUF 32768
#define BUFSZ 49152
#define SMEM_BYTES (SBUF + 2*BUFSZ)   // 131072

// swizzles: 256B-row tiles (16 chunks) and 128B-row tiles (8 chunks)
#define SWZ(r, ch)  ((uint32_t)((r)*256 + ((((ch) ^ ((r)&7)))<<4)))
#define SWZ8(r, ch) ((uint32_t)((r)*128 + ((((ch) ^ ((r)&7)))<<4)))

__device__ __forceinline__ uint32_t smem_u32(const void* p) {
    uint32_t a;
    asm("{ .reg .u64 t; cvta.to.shared.u64 t, %1; cvt.u32.u64 %0, t; }" : "=r"(a) : "l"(p));
    return a;
}
__device__ __forceinline__ void cp_async16(uint32_t dst, const void* src) {
    asm volatile("cp.async.cg.shared.global [%0], [%1], 16;\n" :: "r"(dst), "l"(src));
}
__device__ __forceinline__ void cp_commit() { asm volatile("cp.async.commit_group;\n" ::); }
__device__ __forceinline__ void cp_wait0()  { asm volatile("cp.async.wait_group 0;\n" ::); }

__device__ __forceinline__ void ldmx4(uint32_t a, uint32_t r[4]) {
    asm volatile("ldmatrix.sync.aligned.m8n8.x4.shared.b16 {%0,%1,%2,%3}, [%4];"
        : "=r"(r[0]), "=r"(r[1]), "=r"(r[2]), "=r"(r[3]) : "r"(a));
}
__device__ __forceinline__ void ldmx4t(uint32_t a, uint32_t r[4]) {
    asm volatile("ldmatrix.sync.aligned.m8n8.x4.trans.shared.b16 {%0,%1,%2,%3}, [%4];"
        : "=r"(r[0]), "=r"(r[1]), "=r"(r[2]), "=r"(r[3]) : "r"(a));
}
__device__ __forceinline__ void mma16816(float c[4], const uint32_t a[4],
                                         uint32_t b0, uint32_t b1) {
    asm volatile("mma.sync.aligned.m16n8k16.row.col.f32.f16.f16.f32 "
        "{%0,%1,%2,%3}, {%4,%5,%6,%7}, {%8,%9}, {%0,%1,%2,%3};"
        : "+f"(c[0]), "+f"(c[1]), "+f"(c[2]), "+f"(c[3])
        : "r"(a[0]), "r"(a[1]), "r"(a[2]), "r"(a[3]), "r"(b0), "r"(b1));
}
__device__ __forceinline__ float ex2f(float x) {
    float r; asm("ex2.approx.ftz.f32 %0, %1;" : "=f"(r) : "f"(x)); return r;
}
__device__ __forceinline__ uint32_t f16x2(float hi, float lo) {
    uint32_t d; asm("cvt.rn.f16x2.f32 %0, %1, %2;" : "=r"(d) : "f"(hi), "f"(lo)); return d;
}
__device__ __forceinline__ float2 h2f2(uint32_t d) {
    __half2 h = *(__half2*)&d; return __half22float2(h);
}

// ---------------------------------------------------------------------------
// Split kernels: fp32 -> fp16 hi/lo
// ---------------------------------------------------------------------------
__global__ void split_x_kernel(const float* __restrict__ x) {
    size_t i = ((size_t)blockIdx.x * 256 + threadIdx.x) * 4;
    float4 v = *(const float4*)&x[i];
    __half h0 = __float2half_rn(v.x), h1 = __float2half_rn(v.y);
    __half h2 = __float2half_rn(v.z), h3 = __float2half_rn(v.w);
    __half2 hh[2] = { __halves2half2(h0, h1), __halves2half2(h2, h3) };
    __half2 ll[2] = {
        __floats2half2_rn(v.x - __half2float(h0), v.y - __half2float(h1)),
        __floats2half2_rn(v.z - __half2float(h2), v.w - __half2float(h3)) };
    *(uint2*)&g_xh[i] = *(uint2*)hh;
    *(uint2*)&g_xl[i] = *(uint2*)ll;
}
__global__ void split_w_kernel(const float* __restrict__ Wq,
                               const float* __restrict__ Wk,
                               const float* __restrict__ Wv) {
    const float* W = (blockIdx.y == 0) ? Wq : (blockIdx.y == 1) ? Wk : Wv;
    size_t i = ((size_t)blockIdx.x * 256 + threadIdx.x) * 4;
    size_t o = (size_t)blockIdx.y * SA_D * SA_DH + i;
    float4 v = *(const float4*)&W[i];
    __half h0 = __float2half_rn(v.x), h1 = __float2half_rn(v.y);
    __half h2 = __float2half_rn(v.z), h3 = __float2half_rn(v.w);
    __half2 hh[2] = { __halves2half2(h0, h1), __halves2half2(h2, h3) };
    __half2 ll[2] = {
        __floats2half2_rn(v.x - __half2float(h0), v.y - __half2float(h1)),
        __floats2half2_rn(v.z - __half2float(h2), v.w - __half2float(h3)) };
    *(uint2*)&g_wh[o] = *(uint2*)hh;
    *(uint2*)&g_wl[o] = *(uint2*)ll;
}

// ---------------------------------------------------------------------------
// qkv gemm via fp16 split mma. grid=(128,3), block=128. BM=64, BK=64.
// smem: Xh 8K | Xl 8K | Wh 16K | Wl 16K per buf, x2 = 96KB
// ---------------------------------------------------------------------------
#define GXH 0
#define GXL 8192
#define GWH 16384
#define GWL 32768
#define GBUF 49152
#define GSMEM (2*GBUF)

__device__ __forceinline__ void g_load_chunk(uint32_t dst, int row0, int ym, int kc, int tid) {
    const __half* xh = g_xh;
    const __half* xl = g_xl;
    const __half* wh = g_wh + (size_t)ym * SA_D * SA_DH;
    const __half* wl = g_wl + (size_t)ym * SA_D * SA_DH;
#pragma unroll
    for (int i = 0; i < 4; i++) {            // X: 64 rows x 8 chunks
        int c = tid + i * 128;
        int r = c >> 3, ch = c & 7;
        size_t src = (size_t)(row0 + r) * SA_D + kc * 64 + ch * 8;
        cp_async16(dst + GXH + SWZ8(r, ch), xh + src);
        cp_async16(dst + GXL + SWZ8(r, ch), xl + src);
    }
#pragma unroll
    for (int i = 0; i < 8; i++) {            // W: 64 k-rows x 16 chunks
        int c = tid + i * 128;
        int r = c >> 4, ch = c & 15;
        size_t src = (size_t)(kc * 64 + r) * SA_DH + ch * 8;
        cp_async16(dst + GWH + SWZ(r, ch), wh + src);
        cp_async16(dst + GWL + SWZ(r, ch), wl + src);
    }
}

__global__ __launch_bounds__(128, 1)
void qkv_gemm(const float* dummy) {
    extern __shared__ char smem[];
    const uint32_t sb = smem_u32(smem);
    const int tid = threadIdx.x, wid = tid >> 5, lane = tid & 31;
    const int g = lane >> 2, cq = lane & 3;
    const int row0 = blockIdx.x * BM;
    const int ym = blockIdx.y;
    const int rowa = wid * 16 + (lane & 15);
    const int chq0 = lane >> 4;
    const int quarter = lane >> 3;
    const int kj_sub = quarter >> 1;
    const int k_half = quarter & 1;
    const int rk = lane & 7;
    const int rwo = k_half * 8 + rk;

    float c[16][4];
#pragma unroll
    for (int n = 0; n < 16; n++)
#pragma unroll
        for (int i = 0; i < 4; i++) c[n][i] = 0.0f;

    g_load_chunk(sb, row0, ym, 0, tid);
    cp_commit();

    for (int kc = 0; kc < SA_D / 64; kc++) {
        cp_wait0();
        __syncthreads();
        const uint32_t buf = sb + (uint32_t)(kc & 1) * GBUF;
        if (kc + 1 < SA_D / 64) {
            g_load_chunk(sb + (uint32_t)((kc + 1) & 1) * GBUF, row0, ym, kc + 1, tid);
            cp_commit();
        }
#pragma unroll
        for (int kt = 0; kt < 4; kt++) {
            uint32_t ah[4], al[4];
            ldmx4(buf + GXH + SWZ8(rowa, kt * 2 + chq0), ah);
            ldmx4(buf + GXL + SWZ8(rowa, kt * 2 + chq0), al);
#pragma unroll
            for (int np = 0; np < 8; np++) {
                uint32_t bh[4], bl[4];
                uint32_t off = SWZ(kt * 16 + rwo, 2 * np + kj_sub);
                ldmx4t(buf + GWH + off, bh);
                ldmx4t(buf + GWL + off, bl);
                mma16816(c[2 * np],     ah, bh[0], bh[1]);
                mma16816(c[2 * np + 1], ah, bh[2], bh[3]);
                mma16816(c[2 * np],     ah, bl[0], bl[1]);
                mma16816(c[2 * np + 1], ah, bl[2], bl[3]);
                mma16816(c[2 * np],     al, bh[0], bh[1]);
                mma16816(c[2 * np + 1], al, bh[2], bh[3]);
            }
        }
    }

    const float qscale = (float)(1.4426950408889634 / 11.313708498984761);
    const int ra = row0 + wid * 16 + g, rb = ra + 8;
#pragma unroll
    for (int n = 0; n < 16; n++) {
        int col = n * 8 + cq * 2;
#pragma unroll
        for (int e = 0; e < 2; e++) {
            int row = e ? rb : ra;
            float v0 = e ? c[n][2] : c[n][0];
            float v1 = e ? c[n][3] : c[n][1];
            size_t idx = (size_t)row * SA_DH + col;
            if (ym == 0) {
                v0 *= qscale; v1 *= qscale;
                __half h0 = __float2half_rn(v0), h1 = __float2half_rn(v1);
                *(__half2*)&g_qh[idx] = __halves2half2(h0, h1);
                *(__half2*)&g_ql[idx] = __floats2half2_rn(v0 - __half2float(h0),
                                                          v1 - __half2float(h1));
            } else if (ym == 1) {
                __half h0 = __float2half_rn(v0), h1 = __float2half_rn(v1);
                *(__half2*)&g_kh[idx] = __halves2half2(h0, h1);
                *(__half2*)&g_kl[idx] = __floats2half2_rn(v0 - __half2float(h0),
                                                          v1 - __half2float(h1));
            } else {
                *(__half2*)&g_v[idx] = __floats2half2_rn(v0, v1);
            }
        }
    }
}

// ---------------------------------------------------------------------------
// Fused flash attention, 8 warps (key-split). grid=128, block=256.
// ---------------------------------------------------------------------------
__device__ __forceinline__ void load_chunk(uint32_t dst, int t, int tid) {
    const size_t key0 = (size_t)t * BN * SA_DH;
#pragma unroll
    for (int i = 0; i < 4; i++) {
        int c = tid + i * 256;
        int r = c >> 4, ch = c & 15;
        uint32_t off = SWZ(r, ch);
        size_t src = key0 + (size_t)r * SA_DH + ch * 8;
        cp_async16(dst + off,         g_kh + src);
        cp_async16(dst + 16384 + off, g_kl + src);
        cp_async16(dst + 32768 + off, g_v  + src);
    }
}

__global__ __launch_bounds__(256, 1)
void attn_kernel(float* __restrict__ out) {
    extern __shared__ char smem[];
    const uint32_t sb = smem_u32(smem);
    const int tid = threadIdx.x, wid = tid >> 5, lane = tid & 31;
    const int g = lane >> 2, cq = lane & 3;
    const int wg = wid & 3, group = wid >> 2;
    const int kb = group * 32;                 // key base within chunk
    const int row0 = blockIdx.x * BM;
    const int wm0 = wg * 16;

    const int rowq = wm0 + (lane & 15);
    const int chq0 = lane >> 4;
    const int quarter = lane >> 3;
    const int kj_sub = quarter >> 1;
    const int k_half = quarter & 1;
    const int rk = lane & 7;
    const int rvo = k_half * 8 + rk;

    {
        const __half* qh = g_qh + (size_t)row0 * SA_DH;
        const __half* ql = g_ql + (size_t)row0 * SA_DH;
#pragma unroll
        for (int i = 0; i < 4; i++) {
            int c = tid + i * 256;
            int r = c >> 4, ch = c & 15;
            uint32_t off = SWZ(r, ch);
            size_t src = (size_t)r * SA_DH + ch * 8;
            cp_async16(sb + SQH + off, qh + src);
            cp_async16(sb + SQL + off, ql + src);
        }
        load_chunk(sb + SBUF, 0, tid);
        cp_commit();
    }

    float o[16][4];
#pragma unroll
    for (int n = 0; n < 16; n++)
#pragma unroll
        for (int i = 0; i < 4; i++) o[n][i] = 0.0f;
    float m0 = -1e30f, m1 = -1e30f, l0 = 0.0f, l1 = 0.0f;

    for (int t = 0; t < NC; t++) {
        cp_wait0();
        __syncthreads();
        const uint32_t buf = sb + SBUF + (uint32_t)(t & 1) * BUFSZ;
        if (t + 1 < NC) {
            load_chunk(sb + SBUF + (uint32_t)((t + 1) & 1) * BUFSZ, t + 1, tid);
            cp_commit();
        }

        // ----- S: 32 keys per group, 4 ntiles -----
        float c[4][4];
#pragma unroll
        for (int j = 0; j < 4; j++)
#pragma unroll
            for (int i = 0; i < 4; i++) c[j][i] = 0.0f;

#pragma unroll
        for (int kt = 0; kt < 8; kt++) {
            uint32_t ah[4], al[4];
            ldmx4(sb + SQH + SWZ(rowq, kt * 2 + chq0), ah);
            ldmx4(sb + SQL + SWZ(rowq, kt * 2 + chq0), al);
            uint32_t bh[2][4], bl[2][4];
#pragma unroll
            for (int np = 0; np < 2; np++) {
                int j = np * 2 + kj_sub;
                uint32_t off = SWZ(kb + j * 8 + rk, kt * 2 + k_half);
                ldmx4(buf + off, bh[np]);
                ldmx4(buf + 16384 + off, bl[np]);
            }
#pragma unroll
            for (int np = 0; np < 2; np++) {
                mma16816(c[2 * np],     ah, bh[np][0], bh[np][1]);
                mma16816(c[2 * np + 1], ah, bh[np][2], bh[np][3]);
                mma16816(c[2 * np],     ah, bl[np][0], bl[np][1]);
                mma16816(c[2 * np + 1], ah, bl[np][2], bl[np][3]);
                mma16816(c[2 * np],     al, bh[np][0], bh[np][1]);
                mma16816(c[2 * np + 1], al, bh[np][2], bh[np][3]);
            }
        }

        // ----- online softmax -----
        float mx0 = -1e30f, mx1 = -1e30f;
#pragma unroll
        for (int j = 0; j < 4; j++) {
            mx0 = fmaxf(mx0, fmaxf(c[j][0], c[j][1]));
            mx1 = fmaxf(mx1, fmaxf(c[j][2], c[j][3]));
        }
        mx0 = fmaxf(mx0, __shfl_xor_sync(0xffffffffu, mx0, 1));
        mx0 = fmaxf(mx0, __shfl_xor_sync(0xffffffffu, mx0, 2));
        mx1 = fmaxf(mx1, __shfl_xor_sync(0xffffffffu, mx1, 1));
        mx1 = fmaxf(mx1, __shfl_xor_sync(0xffffffffu, mx1, 2));
        float nm0 = fmaxf(m0, mx0), nm1 = fmaxf(m1, mx1);
        float a0 = ex2f(m0 - nm0), a1 = ex2f(m1 - nm1);
        m0 = nm0; m1 = nm1;
        l0 *= a0; l1 *= a1;
#pragma unroll
        for (int n = 0; n < 16; n++) {
            o[n][0] *= a0; o[n][1] *= a0;
            o[n][2] *= a1; o[n][3] *= a1;
        }
        uint32_t pp[8];
#pragma unroll
        for (int j = 0; j < 4; j++) {
            float p0 = ex2f(c[j][0] - m0), p1 = ex2f(c[j][1] - m0);
            uint32_t pg = f16x2(p1, p0);
            float2 fb = h2f2(pg); l0 += fb.x + fb.y;
            pp[j * 2] = pg;
            float p2 = ex2f(c[j][2] - m1), p3 = ex2f(c[j][3] - m1);
            uint32_t ph = f16x2(p3, p2);
            float2 fc = h2f2(ph); l1 += fc.x + fc.y;
            pp[j * 2 + 1] = ph;
        }

        // ----- O += P V -----
#pragma unroll
        for (int kt = 0; kt < 2; kt++) {
            uint32_t aP[4] = { pp[4 * kt], pp[4 * kt + 1], pp[4 * kt + 2], pp[4 * kt + 3] };
#pragma unroll
            for (int np = 0; np < 8; np++) {
                uint32_t bv[4];
                ldmx4t(buf + 32768 + SWZ(kb + kt * 16 + rvo, 2 * np + kj_sub), bv);
                mma16816(o[2 * np],     aP, bv[0], bv[1]);
                mma16816(o[2 * np + 1], aP, bv[2], bv[3]);
            }
        }
    }

    // ----- merge groups + write out -----
    l0 += __shfl_xor_sync(0xffffffffu, l0, 1);
    l0 += __shfl_xor_sync(0xffffffffu, l0, 2);
    l1 += __shfl_xor_sync(0xffffffffu, l1, 1);
    l1 += __shfl_xor_sync(0xffffffffu, l1, 2);
    __syncthreads();

    float* Osm = (float*)(smem + SBUF);              // 64 x 132
    float* Msm = (float*)(smem + SBUF + 64 * 132 * 4);
    float* Lsm = Msm + 64;
    const int ral = wm0 + g, rbl = ral + 8;

    if (group == 1) {
        if (cq == 0) {
            Msm[ral] = m0; Lsm[ral] = l0;
            Msm[rbl] = m1; Lsm[rbl] = l1;
        }
#pragma unroll
        for (int n = 0; n < 16; n++) {
            int col = n * 8 + cq * 2;
            *(float2*)&Osm[ral * 132 + col] = make_float2(o[n][0], o[n][1]);
            *(float2*)&Osm[rbl * 132 + col] = make_float2(o[n][2], o[n][3]);
        }
    }
    __syncthreads();
    if (group == 0) {
        float m1a = Msm[ral], l1a = Lsm[ral];
        float m1b = Msm[rbl], l1b = Lsm[rbl];
        float mma_ = fmaxf(m0, m1a), mmb = fmaxf(m1, m1b);
        float a0a = ex2f(m0 - mma_), a1a = ex2f(m1a - mma_);
        float a0b = ex2f(m1 - mmb), a1b = ex2f(m1b - mmb);
        float iva = 1.0f / (l0 * a0a + l1a * a1a);
        float ivb = 1.0f / (l1 * a0b + l1b * a1b);
        const int ra = row0 + ral, rb = row0 + rbl;
#pragma unroll
        for (int n = 0; n < 16; n++) {
            int col = n * 8 + cq * 2;
            float2 qa = *(float2*)&Osm[ral * 132 + col];
            float2 qb = *(float2*)&Osm[rbl * 132 + col];
            *(float2*)&out[(size_t)ra * SA_DH + col] =
                make_float2((o[n][0] * a0a + qa.x * a1a) * iva,
                            (o[n][1] * a0a + qa.y * a1a) * iva);
            *(float2*)&out[(size_t)rb * SA_DH + col] =
                make_float2((o[n][2] * a0b + qb.x * a1b) * ivb,
                            (o[n][3] * a0b + qb.y * a1b) * ivb);
        }
    }
}

// ---------------------------------------------------------------------------
extern "C" void kernel_launch(void* const* d_in, const int* in_sizes, int n_in,
                              void* d_out, int out_size) {
    const float* x  = (const float*)d_in[0];
    const float* Wq = (const float*)d_in[1];
    const float* Wk = (const float*)d_in[2];
    const float* Wv = (const float*)d_in[3];
    float* out = (float*)d_out;

    cudaFuncSetAttribute(attn_kernel, cudaFuncAttributeMaxDynamicSharedMemorySize, SMEM_BYTES);
    cudaFuncSetAttribute(qkv_gemm, cudaFuncAttributeMaxDynamicSharedMemorySize, GSMEM);

    split_x_kernel<<<SA_N * SA_D / 4 / 256, 256>>>(x);
    split_w_kernel<<<dim3(SA_D * SA_DH / 4 / 256, 3), 256>>>(Wq, Wk, Wv);
    qkv_gemm<<<dim3(SA_N / BM, 3), 128, GSMEM>>>(nullptr);
    attn_kernel<<<SA_N / BM, 256, SMEM_BYTES>>>(out);
}

// round 8
// speedup vs baseline: 3.7696x; 1.0628x over previous
#include <cuda_runtime.h>
#include <cuda_fp16.h>
#include <cstdint>
#include <math.h>

typedef unsigned long long u64;

#define SA_N  8192
#define SA_D  1024
#define SA_DH 128
#define BM 64
#define BN 64
#define NC (SA_N/BN)

// fp16 operands
__device__ __align__(16) __half g_qh[SA_N*SA_DH];
__device__ __align__(16) __half g_ql[SA_N*SA_DH];
__device__ __align__(16) __half g_kh[SA_N*SA_DH];
__device__ __align__(16) __half g_kl[SA_N*SA_DH];
__device__ __align__(16) __half g_v [SA_N*SA_DH];
// fp16 split inputs for qkv gemm
__device__ __align__(16) __half g_xh[SA_N*SA_D];
__device__ __align__(16) __half g_xl[SA_N*SA_D];
__device__ __align__(16) __half g_wh[3*SA_D*SA_DH];
__device__ __align__(16) __half g_wl[3*SA_D*SA_DH];

// attn smem: Qhi 16K | Qlo 16K | 3 x {Khi 16K, Klo 16K, V 16K}
#define SQH 0
#define SQL 16384
#define SBUF 32768
#define BUFSZ 49152
#define SMEM_BYTES (SBUF + 3*BUFSZ)   // 180224

#define SWZ(r, ch)  ((uint32_t)((r)*256 + ((((ch) ^ ((r)&7)))<<4)))
#define SWZ8(r, ch) ((uint32_t)((r)*128 + ((((ch) ^ ((r)&7)))<<4)))

__device__ __forceinline__ uint32_t smem_u32(const void* p) {
    uint32_t a;
    asm("{ .reg .u64 t; cvta.to.shared.u64 t, %1; cvt.u32.u64 %0, t; }" : "=r"(a) : "l"(p));
    return a;
}
__device__ __forceinline__ void cp_async16(uint32_t dst, const void* src) {
    asm volatile("cp.async.cg.shared.global [%0], [%1], 16;\n" :: "r"(dst), "l"(src));
}
__device__ __forceinline__ void cp_commit() { asm volatile("cp.async.commit_group;\n" ::); }
__device__ __forceinline__ void cp_waitg(int n) {
    if (n == 0) asm volatile("cp.async.wait_group 0;\n" ::);
    else        asm volatile("cp.async.wait_group 1;\n" ::);
}

__device__ __forceinline__ void ldmx4(uint32_t a, uint32_t r[4]) {
    asm volatile("ldmatrix.sync.aligned.m8n8.x4.shared.b16 {%0,%1,%2,%3}, [%4];"
        : "=r"(r[0]), "=r"(r[1]), "=r"(r[2]), "=r"(r[3]) : "r"(a));
}
__device__ __forceinline__ void ldmx4t(uint32_t a, uint32_t r[4]) {
    asm volatile("ldmatrix.sync.aligned.m8n8.x4.trans.shared.b16 {%0,%1,%2,%3}, [%4];"
        : "=r"(r[0]), "=r"(r[1]), "=r"(r[2]), "=r"(r[3]) : "r"(a));
}
__device__ __forceinline__ void mma16816(float c[4], const uint32_t a[4],
                                         uint32_t b0, uint32_t b1) {
    asm volatile("mma.sync.aligned.m16n8k16.row.col.f32.f16.f16.f32 "
        "{%0,%1,%2,%3}, {%4,%5,%6,%7}, {%8,%9}, {%0,%1,%2,%3};"
        : "+f"(c[0]), "+f"(c[1]), "+f"(c[2]), "+f"(c[3])
        : "r"(a[0]), "r"(a[1]), "r"(a[2]), "r"(a[3]), "r"(b0), "r"(b1));
}
__device__ __forceinline__ float ex2f(float x) {
    float r; asm("ex2.approx.ftz.f32 %0, %1;" : "=f"(r) : "f"(x)); return r;
}
__device__ __forceinline__ uint32_t f16x2(float hi, float lo) {
    uint32_t d; asm("cvt.rn.f16x2.f32 %0, %1, %2;" : "=r"(d) : "f"(hi), "f"(lo)); return d;
}
__device__ __forceinline__ float2 h2f2(uint32_t d) {
    __half2 h = *(__half2*)&d; return __half22float2(h);
}

// ---------------------------------------------------------------------------
// Split kernels
// ---------------------------------------------------------------------------
__global__ void split_x_kernel(const float* __restrict__ x) {
    size_t i = ((size_t)blockIdx.x * 256 + threadIdx.x) * 4;
    float4 v = *(const float4*)&x[i];
    __half h0 = __float2half_rn(v.x), h1 = __float2half_rn(v.y);
    __half h2 = __float2half_rn(v.z), h3 = __float2half_rn(v.w);
    __half2 hh[2] = { __halves2half2(h0, h1), __halves2half2(h2, h3) };
    __half2 ll[2] = {
        __floats2half2_rn(v.x - __half2float(h0), v.y - __half2float(h1)),
        __floats2half2_rn(v.z - __half2float(h2), v.w - __half2float(h3)) };
    *(uint2*)&g_xh[i] = *(uint2*)hh;
    *(uint2*)&g_xl[i] = *(uint2*)ll;
}
__global__ void split_w_kernel(const float* __restrict__ Wq,
                               const float* __restrict__ Wk,
                               const float* __restrict__ Wv) {
    const float* W = (blockIdx.y == 0) ? Wq : (blockIdx.y == 1) ? Wk : Wv;
    size_t i = ((size_t)blockIdx.x * 256 + threadIdx.x) * 4;
    size_t o = (size_t)blockIdx.y * SA_D * SA_DH + i;
    float4 v = *(const float4*)&W[i];
    __half h0 = __float2half_rn(v.x), h1 = __float2half_rn(v.y);
    __half h2 = __float2half_rn(v.z), h3 = __float2half_rn(v.w);
    __half2 hh[2] = { __halves2half2(h0, h1), __halves2half2(h2, h3) };
    __half2 ll[2] = {
        __floats2half2_rn(v.x - __half2float(h0), v.y - __half2float(h1)),
        __floats2half2_rn(v.z - __half2float(h2), v.w - __half2float(h3)) };
    *(uint2*)&g_wh[o] = *(uint2*)hh;
    *(uint2*)&g_wl[o] = *(uint2*)ll;
}

// ---------------------------------------------------------------------------
// qkv gemm (fp16 split mma). grid=(128,3), block=128, 2 CTAs/SM.
// ---------------------------------------------------------------------------
#define GXH 0
#define GXL 8192
#define GWH 16384
#define GWL 32768
#define GBUF 49152
#define GSMEM (2*GBUF)

__device__ __forceinline__ void g_load_chunk(uint32_t dst, int row0, int ym, int kc, int tid) {
    const __half* wh = g_wh + (size_t)ym * SA_D * SA_DH;
    const __half* wl = g_wl + (size_t)ym * SA_D * SA_DH;
#pragma unroll
    for (int i = 0; i < 4; i++) {
        int c = tid + i * 128;
        int r = c >> 3, ch = c & 7;
        size_t src = (size_t)(row0 + r) * SA_D + kc * 64 + ch * 8;
        cp_async16(dst + GXH + SWZ8(r, ch), g_xh + src);
        cp_async16(dst + GXL + SWZ8(r, ch), g_xl + src);
    }
#pragma unroll
    for (int i = 0; i < 8; i++) {
        int c = tid + i * 128;
        int r = c >> 4, ch = c & 15;
        size_t src = (size_t)(kc * 64 + r) * SA_DH + ch * 8;
        cp_async16(dst + GWH + SWZ(r, ch), wh + src);
        cp_async16(dst + GWL + SWZ(r, ch), wl + src);
    }
}

__global__ __launch_bounds__(128, 2)
void qkv_gemm(const float* dummy) {
    extern __shared__ char smem[];
    const uint32_t sb = smem_u32(smem);
    const int tid = threadIdx.x, wid = tid >> 5, lane = tid & 31;
    const int g = lane >> 2, cq = lane & 3;
    const int row0 = blockIdx.x * BM;
    const int ym = blockIdx.y;
    const int rowa = wid * 16 + (lane & 15);
    const int chq0 = lane >> 4;
    const int quarter = lane >> 3;
    const int kj_sub = quarter >> 1;
    const int k_half = quarter & 1;
    const int rk = lane & 7;
    const int rwo = k_half * 8 + rk;

    float c[16][4];
#pragma unroll
    for (int n = 0; n < 16; n++)
#pragma unroll
        for (int i = 0; i < 4; i++) c[n][i] = 0.0f;

    g_load_chunk(sb, row0, ym, 0, tid);
    cp_commit();

    for (int kc = 0; kc < SA_D / 64; kc++) {
        cp_waitg(0);
        __syncthreads();
        const uint32_t buf = sb + (uint32_t)(kc & 1) * GBUF;
        if (kc + 1 < SA_D / 64) {
            g_load_chunk(sb + (uint32_t)((kc + 1) & 1) * GBUF, row0, ym, kc + 1, tid);
            cp_commit();
        }
#pragma unroll
        for (int kt = 0; kt < 4; kt++) {
            uint32_t ah[4], al[4];
            ldmx4(buf + GXH + SWZ8(rowa, kt * 2 + chq0), ah);
            ldmx4(buf + GXL + SWZ8(rowa, kt * 2 + chq0), al);
#pragma unroll
            for (int np = 0; np < 8; np++) {
                uint32_t bh[4], bl[4];
                uint32_t off = SWZ(kt * 16 + rwo, 2 * np + kj_sub);
                ldmx4t(buf + GWH + off, bh);
                ldmx4t(buf + GWL + off, bl);
                mma16816(c[2 * np],     ah, bh[0], bh[1]);
                mma16816(c[2 * np + 1], ah, bh[2], bh[3]);
                mma16816(c[2 * np],     ah, bl[0], bl[1]);
                mma16816(c[2 * np + 1], ah, bl[2], bl[3]);
                mma16816(c[2 * np],     al, bh[0], bh[1]);
                mma16816(c[2 * np + 1], al, bh[2], bh[3]);
            }
        }
    }

    const float qscale = (float)(1.4426950408889634 / 11.313708498984761);
    const int ra = row0 + wid * 16 + g, rb = ra + 8;
#pragma unroll
    for (int n = 0; n < 16; n++) {
        int col = n * 8 + cq * 2;
#pragma unroll
        for (int e = 0; e < 2; e++) {
            int row = e ? rb : ra;
            float v0 = e ? c[n][2] : c[n][0];
            float v1 = e ? c[n][3] : c[n][1];
            size_t idx = (size_t)row * SA_DH + col;
            if (ym == 0) {
                v0 *= qscale; v1 *= qscale;
                __half h0 = __float2half_rn(v0), h1 = __float2half_rn(v1);
                *(__half2*)&g_qh[idx] = __halves2half2(h0, h1);
                *(__half2*)&g_ql[idx] = __floats2half2_rn(v0 - __half2float(h0),
                                                          v1 - __half2float(h1));
            } else if (ym == 1) {
                __half h0 = __float2half_rn(v0), h1 = __float2half_rn(v1);
                *(__half2*)&g_kh[idx] = __halves2half2(h0, h1);
                *(__half2*)&g_kl[idx] = __floats2half2_rn(v0 - __half2float(h0),
                                                          v1 - __half2float(h1));
            } else {
                *(__half2*)&g_v[idx] = __floats2half2_rn(v0, v1);
            }
        }
    }
}

// ---------------------------------------------------------------------------
// Fused flash attention, 8 warps, pipelined S. grid=128, block=256.
// ---------------------------------------------------------------------------
__device__ __forceinline__ void load_chunk(uint32_t dst, int t, int tid) {
    const size_t key0 = (size_t)t * BN * SA_DH;
#pragma unroll
    for (int i = 0; i < 4; i++) {
        int c = tid + i * 256;
        int r = c >> 4, ch = c & 15;
        uint32_t off = SWZ(r, ch);
        size_t src = key0 + (size_t)r * SA_DH + ch * 8;
        cp_async16(dst + off,         g_kh + src);
        cp_async16(dst + 16384 + off, g_kl + src);
        cp_async16(dst + 32768 + off, g_v  + src);
    }
}

__global__ __launch_bounds__(256, 1)
void attn_kernel(float* __restrict__ out) {
    extern __shared__ char smem[];
    const uint32_t sb = smem_u32(smem);
    const int tid = threadIdx.x, wid = tid >> 5, lane = tid & 31;
    const int g = lane >> 2, cq = lane & 3;
    const int wg = wid & 3, group = wid >> 2;
    const int kb = group * 32;
    const int row0 = blockIdx.x * BM;
    const int wm0 = wg * 16;

    const int rowq = wm0 + (lane & 15);
    const int chq0 = lane >> 4;
    const int quarter = lane >> 3;
    const int kj_sub = quarter >> 1;
    const int k_half = quarter & 1;
    const int rk = lane & 7;
    const int rvo = k_half * 8 + rk;

    // prologue: Q + chunk0 (group A), chunk1 (group B)
    {
        const __half* qh = g_qh + (size_t)row0 * SA_DH;
        const __half* ql = g_ql + (size_t)row0 * SA_DH;
#pragma unroll
        for (int i = 0; i < 4; i++) {
            int c = tid + i * 256;
            int r = c >> 4, ch = c & 15;
            uint32_t off = SWZ(r, ch);
            size_t src = (size_t)r * SA_DH + ch * 8;
            cp_async16(sb + SQH + off, qh + src);
            cp_async16(sb + SQL + off, ql + src);
        }
        load_chunk(sb + SBUF, 0, tid);
        cp_commit();
        load_chunk(sb + SBUF + BUFSZ, 1, tid);
        cp_commit();
    }

    auto compute_S = [&](uint32_t buf, float (*c)[4]) {
#pragma unroll
        for (int j = 0; j < 4; j++)
#pragma unroll
            for (int i = 0; i < 4; i++) c[j][i] = 0.0f;
#pragma unroll
        for (int kt = 0; kt < 8; kt++) {
            uint32_t ah[4], al[4];
            ldmx4(sb + SQH + SWZ(rowq, kt * 2 + chq0), ah);
            ldmx4(sb + SQL + SWZ(rowq, kt * 2 + chq0), al);
            uint32_t bh[2][4], bl[2][4];
#pragma unroll
            for (int np = 0; np < 2; np++) {
                int j = np * 2 + kj_sub;
                uint32_t off = SWZ(kb + j * 8 + rk, kt * 2 + k_half);
                ldmx4(buf + off, bh[np]);
                ldmx4(buf + 16384 + off, bl[np]);
            }
#pragma unroll
            for (int np = 0; np < 2; np++) {
                mma16816(c[2 * np],     ah, bh[np][0], bh[np][1]);
                mma16816(c[2 * np + 1], ah, bh[np][2], bh[np][3]);
                mma16816(c[2 * np],     ah, bl[np][0], bl[np][1]);
                mma16816(c[2 * np + 1], ah, bl[np][2], bl[np][3]);
                mma16816(c[2 * np],     al, bh[np][0], bh[np][1]);
                mma16816(c[2 * np + 1], al, bh[np][2], bh[np][3]);
            }
        }
    };

    float o[16][4];
#pragma unroll
    for (int n = 0; n < 16; n++)
#pragma unroll
        for (int i = 0; i < 4; i++) o[n][i] = 0.0f;
    float m0 = -1e30f, m1 = -1e30f, l0 = 0.0f, l1 = 0.0f;

    float cbuf[2][4][4];

    // S(0)
    cp_waitg(1);
    __syncthreads();
    compute_S(sb + SBUF, cbuf[0]);

#pragma unroll 2
    for (int t = 0; t < NC; t++) {
        // prefetch t+2, ensure t+1 resident
        if (t + 2 < NC) {
            load_chunk(sb + SBUF + (uint32_t)((t + 2) % 3) * BUFSZ, t + 2, tid);
            cp_commit();
            cp_waitg(1);
        } else {
            cp_waitg(0);
        }
        __syncthreads();

        // issue S(t+1) early — fills tensor pipe under softmax(t)
        if (t + 1 < NC)
            compute_S(sb + SBUF + (uint32_t)((t + 1) % 3) * BUFSZ, cbuf[(t + 1) & 1]);

        float (*c)[4] = cbuf[t & 1];

        // ----- online softmax on S(t) -----
        float mx0 = -1e30f, mx1 = -1e30f;
#pragma unroll
        for (int j = 0; j < 4; j++) {
            mx0 = fmaxf(mx0, fmaxf(c[j][0], c[j][1]));
            mx1 = fmaxf(mx1, fmaxf(c[j][2], c[j][3]));
        }
        mx0 = fmaxf(mx0, __shfl_xor_sync(0xffffffffu, mx0, 1));
        mx0 = fmaxf(mx0, __shfl_xor_sync(0xffffffffu, mx0, 2));
        mx1 = fmaxf(mx1, __shfl_xor_sync(0xffffffffu, mx1, 1));
        mx1 = fmaxf(mx1, __shfl_xor_sync(0xffffffffu, mx1, 2));
        float nm0 = fmaxf(m0, mx0), nm1 = fmaxf(m1, mx1);
        unsigned vote = __ballot_sync(0xffffffffu, (nm0 > m0) || (nm1 > m1));
        if (vote) {
            float a0 = ex2f(m0 - nm0), a1 = ex2f(m1 - nm1);
            m0 = nm0; m1 = nm1;
            l0 *= a0; l1 *= a1;
#pragma unroll
            for (int n = 0; n < 16; n++) {
                o[n][0] *= a0; o[n][1] *= a0;
                o[n][2] *= a1; o[n][3] *= a1;
            }
        }
        uint32_t pp[8];
#pragma unroll
        for (int j = 0; j < 4; j++) {
            float p0 = ex2f(c[j][0] - m0), p1 = ex2f(c[j][1] - m0);
            uint32_t pg = f16x2(p1, p0);
            float2 fb = h2f2(pg); l0 += fb.x + fb.y;
            pp[j * 2] = pg;
            float p2 = ex2f(c[j][2] - m1), p3 = ex2f(c[j][3] - m1);
            uint32_t ph = f16x2(p3, p2);
            float2 fc = h2f2(ph); l1 += fc.x + fc.y;
            pp[j * 2 + 1] = ph;
        }

        // ----- O += P V (reads V(t) buffer) -----
        const uint32_t vbuf = sb + SBUF + (uint32_t)(t % 3) * BUFSZ + 32768;
#pragma unroll
        for (int kt = 0; kt < 2; kt++) {
            uint32_t aP[4] = { pp[4 * kt], pp[4 * kt + 1], pp[4 * kt + 2], pp[4 * kt + 3] };
#pragma unroll
            for (int np = 0; np < 8; np++) {
                uint32_t bv[4];
                ldmx4t(vbuf + SWZ(kb + kt * 16 + rvo, 2 * np + kj_sub), bv);
                mma16816(o[2 * np],     aP, bv[0], bv[1]);
                mma16816(o[2 * np + 1], aP, bv[2], bv[3]);
            }
        }
    }

    // ----- merge groups + write out -----
    l0 += __shfl_xor_sync(0xffffffffu, l0, 1);
    l0 += __shfl_xor_sync(0xffffffffu, l0, 2);
    l1 += __shfl_xor_sync(0xffffffffu, l1, 1);
    l1 += __shfl_xor_sync(0xffffffffu, l1, 2);
    __syncthreads();

    float* Osm = (float*)(smem + SBUF);
    float* Msm = (float*)(smem + SBUF + 64 * 132 * 4);
    float* Lsm = Msm + 64;
    const int ral = wm0 + g, rbl = ral + 8;

    if (group == 1) {
        if (cq == 0) {
            Msm[ral] = m0; Lsm[ral] = l0;
            Msm[rbl] = m1; Lsm[rbl] = l1;
        }
#pragma unroll
        for (int n = 0; n < 16; n++) {
            int col = n * 8 + cq * 2;
            *(float2*)&Osm[ral * 132 + col] = make_float2(o[n][0], o[n][1]);
            *(float2*)&Osm[rbl * 132 + col] = make_float2(o[n][2], o[n][3]);
        }
    }
    __syncthreads();
    if (group == 0) {
        float m1a = Msm[ral], l1a = Lsm[ral];
        float m1b = Msm[rbl], l1b = Lsm[rbl];
        float mma_ = fmaxf(m0, m1a), mmb = fmaxf(m1, m1b);
        float a0a = ex2f(m0 - mma_), a1a = ex2f(m1a - mma_);
        float a0b = ex2f(m1 - mmb), a1b = ex2f(m1b - mmb);
        float iva = 1.0f / (l0 * a0a + l1a * a1a);
        float ivb = 1.0f / (l1 * a0b + l1b * a1b);
        const int ra = row0 + ral, rb = row0 + rbl;
#pragma unroll
        for (int n = 0; n < 16; n++) {
            int col = n * 8 + cq * 2;
            float2 qa = *(float2*)&Osm[ral * 132 + col];
            float2 qb = *(float2*)&Osm[rbl * 132 + col];
            *(float2*)&out[(size_t)ra * SA_DH + col] =
                make_float2((o[n][0] * a0a + qa.x * a1a) * iva,
                            (o[n][1] * a0a + qa.y * a1a) * iva);
            *(float2*)&out[(size_t)rb * SA_DH + col] =
                make_float2((o[n][2] * a0b + qb.x * a1b) * ivb,
                            (o[n][3] * a0b + qb.y * a1b) * ivb);
        }
    }
}

// ---------------------------------------------------------------------------
extern "C" void kernel_launch(void* const* d_in, const int* in_sizes, int n_in,
                              void* d_out, int out_size) {
    const float* x  = (const float*)d_in[0];
    const float* Wq = (const float*)d_in[1];
    const float* Wk = (const float*)d_in[2];
    const float* Wv = (const float*)d_in[3];
    float* out = (float*)d_out;

    cudaFuncSetAttribute(attn_kernel, cudaFuncAttributeMaxDynamicSharedMemorySize, SMEM_BYTES);
    cudaFuncSetAttribute(qkv_gemm, cudaFuncAttributeMaxDynamicSharedMemorySize, GSMEM);

    split_x_kernel<<<SA_N * SA_D / 4 / 256, 256>>>(x);
    split_w_kernel<<<dim3(SA_D * SA_DH / 4 / 256, 3), 256>>>(Wq, Wk, Wv);
    qkv_gemm<<<dim3(SA_N / BM, 3), 128, GSMEM>>>(nullptr);
    attn_kernel<<<SA_N / BM, 256, SMEM_BYTES>>>(out);
}